// round 6
// baseline (speedup 1.0000x reference)
#include <cuda_runtime.h>
#include <cstdint>

// ---------------------------------------------------------------------------
// Problem constants
//   B=8, C_IN=256, DIM=64, HEADS=8, D_IN=128, DKQ=8, DV=16, QKV=32
//   N = B*DIM*DIM = 32768 "pixels"; sequences: 512 of length 64
// ---------------------------------------------------------------------------
#define NT 32768
#define EPSV 1e-5f

__device__ float  g_y1[128 * NT];      // conv-in raw output, layout [c][b][w][h]
__device__ float  g_qkv[256 * NT];     // qkv, layout [o][bw][pos]
__device__ float  g_outatt[256 * NT];  // attention out (sve ch 0..127, sv 128..255)
__device__ float  g_x3[128 * NT];      // att1 combined (input to qkv2 GEMM)
__device__ float  g_y2[256 * NT];      // conv-out raw output [o][n1]
// stats offsets: convin @0(256) att1 @256(48) out1 @304(512) att2 @816(48)
//                out2 @864(512) convout @1376(512)
__device__ double g_st[1888];
__device__ float  g_sb[1888];

// Precomputed rel-embedding tables, double-buffered per direction
__device__ float g_Tq[2][8 * 64], g_Tk[2][8 * 64];
__device__ float g_Sq[2][36 * 64], g_Sk[2][36 * 64];

__device__ const int c_pi[36] = {0,0,0,0,0,0,0,0, 1,1,1,1,1,1,1, 2,2,2,2,2,2,
                                 3,3,3,3,3, 4,4,4,4, 5,5,5, 6,6, 7};
__device__ const int c_pj[36] = {0,1,2,3,4,5,6,7, 1,2,3,4,5,6,7, 2,3,4,5,6,7,
                                 3,4,5,6,7, 4,5,6,7, 5,6,7, 6,7, 7};

__global__ void zero_stats() {
    int i = blockIdx.x * 256 + threadIdx.x;
    if (i < 1888) g_st[i] = 0.0;
}

__global__ void make_scale(int stoff, const float* __restrict__ gamma,
                           const float* __restrict__ beta, int sboff, int C, float invN) {
    int t = blockIdx.x * 64 + threadIdx.x;
    if (t >= C) return;
    double mean = g_st[stoff + t] * (double)invN;
    double var  = g_st[stoff + C + t] * (double)invN - mean * mean;
    float s = gamma[t] * rsqrtf((float)var + EPSV);
    g_sb[sboff + t]     = s;
    g_sb[sboff + C + t] = beta[t] - (float)mean * s;
}

// ---------------------------------------------------------------------------
// 3xTF32 helpers
// ---------------------------------------------------------------------------
__device__ __forceinline__ void split_tf32(float x, float& hi, float& lo) {
    uint32_t h;
    asm("cvt.rna.tf32.f32 %0, %1;" : "=r"(h) : "f"(x));
    float hf = __uint_as_float(h);
    uint32_t l;
    asm("cvt.rna.tf32.f32 %0, %1;" : "=r"(l) : "f"(x - hf));
    hi = hf;
    lo = __uint_as_float(l);
}

#define MMA_TF32(c, a0, a1, a2, a3, b0, b1)                                    \
    asm volatile(                                                              \
        "mma.sync.aligned.m16n8k8.row.col.f32.tf32.tf32.f32 "                  \
        "{%0,%1,%2,%3}, {%4,%5,%6,%7}, {%8,%9}, {%0,%1,%2,%3};"                \
        : "+f"(c[0]), "+f"(c[1]), "+f"(c[2]), "+f"(c[3])                       \
        : "r"(a0), "r"(a1), "r"(a2), "r"(a3), "r"(b0), "r"(b1))

// ---------------------------------------------------------------------------
// GEMM via 3xTF32 mma.sync, fragment-major smem layout.
//   A frag (16m x 8k):  addr = frag*128 + lane*4 + reg  -> LDS.128 = a0..a3
//   B frag (8k x 8n):   addr = frag*66  + lane*2 + reg  -> LDS.64  = b0,b1
// MODE 0 conv-in (gather x_in, scatter to y1 + stats), 1 qkv (BN+relu at
// load), 2 qkv plain (reads x3), 3 conv-out (fused combine2 at load, +stats)
// Block tile 128x128, k-chunk 16; 8 warps, warp tile 64(m) x 32(n).
// Register-staged pipeline: gmem loads for chunk c+1 issue before compute(c).
// ---------------------------------------------------------------------------
template <int MODE>
__device__ __forceinline__ float4 gemm_loadB(const float* __restrict__ Bext,
                                             int n0, int k, int nn) {
    if (MODE == 0) {
        return *(const float4*)&Bext[(n0 >> 12) * 1048576 + k * 4096 + (n0 & 4095) + nn];
    } else if (MODE == 3) {
        float4 a = *(const float4*)&g_outatt[k * NT + n0 + nn];
        float4 b = *(const float4*)&g_outatt[(128 + k) * NT + n0 + nn];
        float sA = g_sb[864 + k],       bA = g_sb[864 + 256 + k];
        float sB = g_sb[864 + 128 + k], bB = g_sb[864 + 256 + 128 + k];
        float4 v;
        v.x = fmaxf(a.x * sA + bA + b.x * sB + bB, 0.f);
        v.y = fmaxf(a.y * sA + bA + b.y * sB + bB, 0.f);
        v.z = fmaxf(a.z * sA + bA + b.z * sB + bB, 0.f);
        v.w = fmaxf(a.w * sA + bA + b.w * sB + bB, 0.f);
        return v;
    } else {
        const float* Bp = (MODE == 1) ? g_y1 : g_x3;
        float4 v = *(const float4*)&Bp[k * NT + n0 + nn];
        if (MODE == 1) {
            float s = g_sb[k], bi = g_sb[128 + k];
            v.x = fmaxf(fmaf(v.x, s, bi), 0.f);
            v.y = fmaxf(fmaf(v.y, s, bi), 0.f);
            v.z = fmaxf(fmaf(v.z, s, bi), 0.f);
            v.w = fmaxf(fmaf(v.w, s, bi), 0.f);
        }
        return v;
    }
}

template <int MODE>
__global__ void __launch_bounds__(256) gemm_k(const float* __restrict__ A,
                                              const float* __restrict__ Bext, int K) {
    __shared__ float Ash[2048], Asl[2048];     // 16 frags * 128
    __shared__ float Bsh[2112], Bsl[2112];     // 32 frags * 66
    __shared__ float ssum[128], ssq[128];
    const int n0 = blockIdx.x * 128;
    const int m0 = blockIdx.y * 128;
    const int tid = threadIdx.x;
    const int warp = tid >> 5, lane = tid & 31;
    const int lq = lane & 3, lr = lane >> 2;
    const int mb = (warp & 1) * 64;
    const int nb = (warp >> 1) * 32;

    float* Cp = (MODE == 0) ? g_y1 : ((MODE == 3) ? g_y2 : g_qkv);

    // staging coordinates (2 rounds of 256 threads each)
    const int arow0 = tid >> 2,        ac4 = (tid & 3) * 4;       // round r adds 64 rows
    const int bkr0  = tid >> 5,        bn4 = (tid & 31) * 4;      // round r adds 8 k-rows

    float acc[4][4][4];
#pragma unroll
    for (int mt = 0; mt < 4; mt++)
#pragma unroll
        for (int nt = 0; nt < 4; nt++)
#pragma unroll
            for (int c = 0; c < 4; c++) acc[mt][nt][c] = 0.f;

    float4 aR[2], bR[2];
    // prologue: load chunk 0
#pragma unroll
    for (int r = 0; r < 2; r++) {
        aR[r] = *(const float4*)&A[(m0 + arow0 + r * 64) * K + ac4];
        bR[r] = gemm_loadB<MODE>(Bext, n0, bkr0 + r * 8, bn4);
    }

    const int nchunk = K >> 4;
    for (int c0 = 0; c0 < nchunk; c0++) {
        // ---- convert regs -> fragment-major smem ----
#pragma unroll
        for (int r = 0; r < 2; r++) {
            int row = arow0 + r * 64;
            int fl  = ((ac4 >> 3) & 1) * 8 + (row >> 4);
            int rg  = ((ac4 >> 2) & 1) * 2 + ((row >> 3) & 1);
            int base = fl * 128 + (row & 7) * 16 + rg;
            float h, l;
            split_tf32(aR[r].x, h, l); Ash[base + 0]  = h; Asl[base + 0]  = l;
            split_tf32(aR[r].y, h, l); Ash[base + 4]  = h; Asl[base + 4]  = l;
            split_tf32(aR[r].z, h, l); Ash[base + 8]  = h; Asl[base + 8]  = l;
            split_tf32(aR[r].w, h, l); Ash[base + 12] = h; Asl[base + 12] = l;
        }
#pragma unroll
        for (int r = 0; r < 2; r++) {
            int kr = bkr0 + r * 8;
            int fl = ((kr >> 3) & 1) * 16 + (bn4 >> 3);
            int rg = (kr >> 2) & 1;
            int base = fl * 66 + ((bn4 & 7) * 4 + (kr & 3)) * 2 + rg;
            float h, l;
            split_tf32(bR[r].x, h, l); Bsh[base + 0]  = h; Bsl[base + 0]  = l;
            split_tf32(bR[r].y, h, l); Bsh[base + 8]  = h; Bsl[base + 8]  = l;
            split_tf32(bR[r].z, h, l); Bsh[base + 16] = h; Bsl[base + 16] = l;
            split_tf32(bR[r].w, h, l); Bsh[base + 24] = h; Bsl[base + 24] = l;
        }
        __syncthreads();

        // ---- prefetch next chunk into regs (overlaps MMA compute) ----
        if (c0 + 1 < nchunk) {
            int k0n = (c0 + 1) * 16;
#pragma unroll
            for (int r = 0; r < 2; r++) {
                aR[r] = *(const float4*)&A[(m0 + arow0 + r * 64) * K + k0n + ac4];
                bR[r] = gemm_loadB<MODE>(Bext, n0, k0n + bkr0 + r * 8, bn4);
            }
        }

        // ---- compute ----
#pragma unroll
        for (int ks = 0; ks < 2; ks++) {
            float2 bhv[4], blv[4];
#pragma unroll
            for (int nt = 0; nt < 4; nt++) {
                int ab = (ks * 16 + (nb >> 3) + nt) * 66 + lane * 2;
                bhv[nt] = *(const float2*)&Bsh[ab];
                blv[nt] = *(const float2*)&Bsl[ab];
            }
#pragma unroll
            for (int mt = 0; mt < 4; mt++) {
                int aa = (ks * 8 + (mb >> 4) + mt) * 128 + lane * 4;
                float4 ha = *(const float4*)&Ash[aa];
                float4 la = *(const float4*)&Asl[aa];
                uint32_t ah0 = __float_as_uint(ha.x), ah1 = __float_as_uint(ha.y);
                uint32_t ah2 = __float_as_uint(ha.z), ah3 = __float_as_uint(ha.w);
                uint32_t al0 = __float_as_uint(la.x), al1 = __float_as_uint(la.y);
                uint32_t al2 = __float_as_uint(la.z), al3 = __float_as_uint(la.w);
#pragma unroll
                for (int nt = 0; nt < 4; nt++) {
                    uint32_t bh0 = __float_as_uint(bhv[nt].x);
                    uint32_t bh1 = __float_as_uint(bhv[nt].y);
                    uint32_t bl0 = __float_as_uint(blv[nt].x);
                    uint32_t bl1 = __float_as_uint(blv[nt].y);
                    MMA_TF32(acc[mt][nt], ah0, ah1, ah2, ah3, bh0, bh1);
                    MMA_TF32(acc[mt][nt], al0, al1, al2, al3, bh0, bh1);
                    MMA_TF32(acc[mt][nt], ah0, ah1, ah2, ah3, bl0, bl1);
                }
            }
        }
        __syncthreads();
    }

    if (MODE == 0 || MODE == 3) {
        for (int t = tid; t < 128; t += 256) { ssum[t] = 0.f; ssq[t] = 0.f; }
        __syncthreads();
    }

    if (MODE == 0) {
        const int bb = n0 >> 12, hw0 = n0 & 4095;
#pragma unroll
        for (int mt = 0; mt < 4; mt++) {
#pragma unroll
            for (int half = 0; half < 2; half++) {
                int o = mb + mt * 16 + lr + half * 8;  // m0 == 0
                float rs = 0.f, rq = 0.f;
#pragma unroll
                for (int nt = 0; nt < 4; nt++) {
#pragma unroll
                    for (int cc = 0; cc < 2; cc++) {
                        int hw = hw0 + nb + nt * 8 + 2 * lq + cc;
                        float v = acc[mt][nt][half * 2 + cc];
                        Cp[o * NT + bb * 4096 + (hw & 63) * 64 + (hw >> 6)] = v;
                        rs += v; rq += v * v;
                    }
                }
                atomicAdd(&ssum[o], rs);
                atomicAdd(&ssq[o], rq);
            }
        }
    } else {
#pragma unroll
        for (int mt = 0; mt < 4; mt++) {
#pragma unroll
            for (int half = 0; half < 2; half++) {
                int o = m0 + mb + mt * 16 + lr + half * 8;
                float rs = 0.f, rq = 0.f;
#pragma unroll
                for (int nt = 0; nt < 4; nt++) {
                    float2 v2 = make_float2(acc[mt][nt][half * 2], acc[mt][nt][half * 2 + 1]);
                    *(float2*)&Cp[o * NT + n0 + nb + nt * 8 + 2 * lq] = v2;
                    if (MODE == 3) { rs += v2.x + v2.y; rq += v2.x * v2.x + v2.y * v2.y; }
                }
                if (MODE == 3) {
                    atomicAdd(&ssum[o - m0], rs);
                    atomicAdd(&ssq[o - m0], rq);
                }
            }
        }
    }

    if (MODE == 0 || MODE == 3) {
        __syncthreads();
        const int base = (MODE == 0) ? 0 : 1376;
        const int Csz  = (MODE == 0) ? 128 : 256;
        if (tid < 128) {
            atomicAdd(&g_st[base + m0 + tid], (double)ssum[tid]);
            atomicAdd(&g_st[base + Csz + m0 + tid], (double)ssq[tid]);
        }
    }
}

// ---------------------------------------------------------------------------
// prep_S: precompute sliding-window tables of the rel embedding (grid-stride).
// ---------------------------------------------------------------------------
__global__ void __launch_bounds__(256) prep_S(const float* __restrict__ rel, int dir) {
    __shared__ float r[16][127];
    for (int t = threadIdx.x; t < 16 * 127; t += 256) r[t / 127][t % 127] = rel[t];
    __syncthreads();
    const int g0 = blockIdx.x * 256 + threadIdx.x;
    const int gs = gridDim.x * 256;
    for (int t = g0; t < 1024; t += gs) {
        int which = t >> 9, i = (t >> 6) & 7, d = t & 63;
        const float* rr = r[which * 8 + i];
        float s = 0.f;
        for (int u = 0; u < 64; u++) s += rr[d + u];
        (which ? g_Tk[dir] : g_Tq[dir])[i * 64 + d] = s;
    }
    for (int t = g0; t < 4608; t += gs) {
        int which = t / 2304, rem = t % 2304, p = rem >> 6, d = rem & 63;
        const float* a = r[which * 8 + c_pi[p]];
        const float* b = r[which * 8 + c_pj[p]];
        float s = 0.f;
        for (int u = 0; u < 64; u++) s = fmaf(a[d + u], b[d + u], s);
        (which ? g_Sk[dir] : g_Sq[dir])[p * 64 + d] = s;
    }
}

// ---------------------------------------------------------------------------
// att_stats: BN statistics of qr/kr/dots without materializing logits.
// ---------------------------------------------------------------------------
__global__ void __launch_bounds__(256) att_stats(int stoff, int dir) {
    const int bw = blockIdx.x, tid = threadIdx.x;
    __shared__ float qT[8][512];   // [h][d*8 + i]
    __shared__ float kT[8][512];
    __shared__ float rsq[8][8], rsk[8][8], tqs[8][8], tks[8][8];

    for (int t = tid; t < 8192; t += 256) {
        int which = t >> 12, o = (t >> 6) & 63, d = t & 63;
        float v = g_qkv[(which * 64 + o) * NT + bw * 64 + d];
        int h = o & 7, i = o >> 3;
        if (which == 0) qT[h][d * 8 + i] = v; else kT[h][d * 8 + i] = v;
    }
    __syncthreads();

    const int h = tid >> 5, lane = tid & 31;
    const float* Tq = g_Tq[dir];
    const float* Tk = g_Tk[dir];
    const float* Sq = g_Sq[dir];
    const float* Sk = g_Sk[dir];
    if (lane < 8) {
        float s = 0.f;
        for (int d = 0; d < 64; d++) s += qT[h][d * 8 + lane];
        rsq[h][lane] = s;
    } else if (lane < 16) {
        int i = lane - 8; float s = 0.f;
        for (int d = 0; d < 64; d++) s += kT[h][d * 8 + i];
        rsk[h][i] = s;
    } else if (lane < 24) {
        int i = lane - 16; float s = 0.f;
        for (int d = 0; d < 64; d++) s = fmaf(qT[h][d * 8 + i], __ldg(&Tq[i * 64 + d]), s);
        tqs[h][i] = s;
    } else {
        int i = lane - 24; float s = 0.f;
        for (int d = 0; d < 64; d++) s = fmaf(kT[h][d * 8 + i], __ldg(&Tk[i * 64 + d]), s);
        tks[h][i] = s;
    }

    float dsq = 0.f, wq = 0.f, wk = 0.f;
    for (int p = lane; p < 36; p += 32) {
        int i = c_pi[p], i2 = c_pj[p];
        float m = (i == i2) ? 1.f : 2.f;
        float gq = 0.f, wqp = 0.f, gk = 0.f, wkp = 0.f;
        for (int d = 0; d < 64; d++) {
            float pq = qT[h][d * 8 + i] * qT[h][d * 8 + i2];
            gq += pq; wqp = fmaf(pq, __ldg(&Sq[p * 64 + d]), wqp);
            float pk = kT[h][d * 8 + i] * kT[h][d * 8 + i2];
            gk += pk; wkp = fmaf(pk, __ldg(&Sk[p * 64 + d]), wkp);
        }
        dsq = fmaf(m * gq, gk, dsq); wq = fmaf(m, wqp, wq); wk = fmaf(m, wkp, wk);
    }
#pragma unroll
    for (int off = 16; off; off >>= 1) {
        dsq += __shfl_xor_sync(~0u, dsq, off);
        wq  += __shfl_xor_sync(~0u, wq,  off);
        wk  += __shfl_xor_sync(~0u, wk,  off);
    }
    __syncwarp();
    if (lane == 0) {
        float ds = 0.f, qs = 0.f, ks = 0.f;
#pragma unroll
        for (int i = 0; i < 8; i++) {
            ds = fmaf(rsq[h][i], rsk[h][i], ds);
            qs += tqs[h][i]; ks += tks[h][i];
        }
        atomicAdd(&g_st[stoff + h * 3 + 0], (double)qs);
        atomicAdd(&g_st[stoff + h * 3 + 1], (double)ks);
        atomicAdd(&g_st[stoff + h * 3 + 2], (double)ds);
        atomicAdd(&g_st[stoff + 24 + h * 3 + 0], (double)wq);
        atomicAdd(&g_st[stoff + 24 + h * 3 + 1], (double)wk);
        atomicAdd(&g_st[stoff + 24 + h * 3 + 2], (double)dsq);
    }
}

// ---------------------------------------------------------------------------
// att_pass2: logits (BN applied) -> softmax -> sv & sve.  Conflict-free:
// Phase A: warp = 8 d-rows, lane = j (stride-1 rel reads, broadcast q/k).
// Phase B: warp = 2 i-channels, lane = d (stride-1 rel, pitch-65 sat).
// ---------------------------------------------------------------------------
__global__ void __launch_bounds__(256) att_pass2(const float* __restrict__ rel,
                                                 int sba, int sto) {
    const int bw = blockIdx.x, h = blockIdx.y, tid = threadIdx.x;
    const int warp = tid >> 5, lane = tid & 31;
    __shared__ float sq[8][65], sk[8][65], svv[16][65];
    __shared__ float srel[32][129];
    __shared__ float sat[64][65];

#pragma unroll
    for (int r = 0; r < 8; r++) {
        int t = tid + r * 256;
        int o = t >> 6, d = t & 63;
        float v = g_qkv[(o * 8 + h) * NT + bw * 64 + d];
        if (o < 8) sq[o][d] = v;
        else if (o < 16) sk[o - 8][d] = v;
        else svv[o - 16][d] = v;
    }
    for (int t = tid; t < 32 * 127; t += 256) srel[t / 127][t % 127] = rel[t];
    const float s0 = g_sb[sba + h * 3], s1v = g_sb[sba + h * 3 + 1], s2v = g_sb[sba + h * 3 + 2];
    const float bsum = g_sb[sba + 24 + h * 3] + g_sb[sba + 24 + h * 3 + 1]
                     + g_sb[sba + 24 + h * 3 + 2];
    __syncthreads();

    {   // ---- Phase A: logits + softmax.  j0 = lane, j1 = lane + 32. ----
        float kk0[8], kk1[8];
#pragma unroll
        for (int i = 0; i < 8; i++) {
            kk0[i] = sk[i][lane];
            kk1[i] = sk[i][lane + 32];
        }
        const int dbase = warp * 8;
#pragma unroll
        for (int r = 0; r < 8; r++) {
            const int d = dbase + r;
            const int m0 = d - lane + 63;   // in [32,126]; m0-32 in [0,94]
            float qr0 = 0, kr0 = 0, dt0 = 0, qr1 = 0, kr1 = 0, dt1 = 0;
#pragma unroll
            for (int i = 0; i < 8; i++) {
                float qi  = sq[i][d];       // broadcast
                float kdi = sk[i][d];       // broadcast
                float rq0 = srel[i][m0],     rq1 = srel[i][m0 - 32];
                float rk0 = srel[8 + i][m0], rk1 = srel[8 + i][m0 - 32];
                qr0 = fmaf(qi, rq0, qr0);   qr1 = fmaf(qi, rq1, qr1);
                kr0 = fmaf(kdi, rk0, kr0);  kr1 = fmaf(kdi, rk1, kr1);
                dt0 = fmaf(qi, kk0[i], dt0); dt1 = fmaf(qi, kk1[i], dt1);
            }
            float l0 = qr0 * s0 + kr0 * s1v + dt0 * s2v + bsum;
            float l1 = qr1 * s0 + kr1 * s1v + dt1 * s2v + bsum;
            float mx = fmaxf(l0, l1);
#pragma unroll
            for (int off = 16; off; off >>= 1)
                mx = fmaxf(mx, __shfl_xor_sync(~0u, mx, off));
            float e0 = __expf(l0 - mx), e1 = __expf(l1 - mx);
            float se = e0 + e1;
#pragma unroll
            for (int off = 16; off; off >>= 1)
                se += __shfl_xor_sync(~0u, se, off);
            float inv = 1.f / se;
            sat[d][lane]      = e0 * inv;
            sat[d][lane + 32] = e1 * inv;
        }
    }
    __syncthreads();

    {   // ---- Phase B: sv & sve.  i0 = 2*warp, i1 = i0+1; da = lane, db = lane+32.
        const int i0 = warp * 2, i1 = i0 + 1;
        const int da = lane, db = lane + 32;
        float av0a = 0, av0b = 0, av1a = 0, av1b = 0;
        float ae0a = 0, ae0b = 0, ae1a = 0, ae1b = 0;
        const float* r0 = &srel[16 + i0][0];
        const float* r1 = &srel[16 + i1][0];
#pragma unroll 4
        for (int j = 0; j < 64; j++) {
            float Aa = sat[da][j];          // stride 65 across lanes: cf
            float Ab = sat[db][j];
            float v0 = svv[i0][j], v1 = svv[i1][j];   // broadcast
            float r0a = r0[da - j + 63], r0b = r0[db - j + 63];
            float r1a = r1[da - j + 63], r1b = r1[db - j + 63];
            av0a = fmaf(Aa, v0, av0a);  av0b = fmaf(Ab, v0, av0b);
            av1a = fmaf(Aa, v1, av1a);  av1b = fmaf(Ab, v1, av1b);
            ae0a = fmaf(Aa, r0a, ae0a); ae0b = fmaf(Ab, r0b, ae0b);
            ae1a = fmaf(Aa, r1a, ae1a); ae1b = fmaf(Ab, r1b, ae1b);
        }
        const int ch0 = h * 16 + i0, ch1 = h * 16 + i1;
        g_outatt[ch0 * NT + bw * 64 + da] = ae0a;
        g_outatt[ch0 * NT + bw * 64 + db] = ae0b;
        g_outatt[ch1 * NT + bw * 64 + da] = ae1a;
        g_outatt[ch1 * NT + bw * 64 + db] = ae1b;
        g_outatt[(128 + ch0) * NT + bw * 64 + da] = av0a;
        g_outatt[(128 + ch0) * NT + bw * 64 + db] = av0b;
        g_outatt[(128 + ch1) * NT + bw * 64 + da] = av1a;
        g_outatt[(128 + ch1) * NT + bw * 64 + db] = av1b;

        float se0 = ae0a + ae0b, qe0 = ae0a * ae0a + ae0b * ae0b;
        float se1 = ae1a + ae1b, qe1 = ae1a * ae1a + ae1b * ae1b;
        float sv0 = av0a + av0b, qv0 = av0a * av0a + av0b * av0b;
        float sv1 = av1a + av1b, qv1 = av1a * av1a + av1b * av1b;
#pragma unroll
        for (int off = 16; off; off >>= 1) {
            se0 += __shfl_xor_sync(~0u, se0, off); qe0 += __shfl_xor_sync(~0u, qe0, off);
            se1 += __shfl_xor_sync(~0u, se1, off); qe1 += __shfl_xor_sync(~0u, qe1, off);
            sv0 += __shfl_xor_sync(~0u, sv0, off); qv0 += __shfl_xor_sync(~0u, qv0, off);
            sv1 += __shfl_xor_sync(~0u, sv1, off); qv1 += __shfl_xor_sync(~0u, qv1, off);
        }
        if (lane == 0) {
            atomicAdd(&g_st[sto + ch0], (double)se0);
            atomicAdd(&g_st[sto + ch1], (double)se1);
            atomicAdd(&g_st[sto + 256 + ch0], (double)qe0);
            atomicAdd(&g_st[sto + 256 + ch1], (double)qe1);
            atomicAdd(&g_st[sto + 128 + ch0], (double)sv0);
            atomicAdd(&g_st[sto + 128 + ch1], (double)sv1);
            atomicAdd(&g_st[sto + 256 + 128 + ch0], (double)qv0);
            atomicAdd(&g_st[sto + 256 + 128 + ch1], (double)qv1);
        }
    }
}

// combine att1: x3[c][b][h][w] = bn(sve) + bn(sv), with h<->w transpose
__global__ void __launch_bounds__(256) combine1() {
    const int c = blockIdx.x, b = blockIdx.y, tid = threadIdx.x;
    __shared__ float tile[64][65];
    const float sA = g_sb[304 + c],        bA = g_sb[304 + 256 + c];
    const float sB = g_sb[304 + c + 128],  bB = g_sb[304 + 256 + c + 128];
    const float* pA = g_outatt + c * NT + b * 4096;
    const float* pB = g_outatt + (c + 128) * NT + b * 4096;
    for (int t = tid; t < 4096; t += 256)
        tile[t >> 6][t & 63] = pA[t] * sA + bA + pB[t] * sB + bB;
    __syncthreads();
    float* q = g_x3 + c * NT + b * 4096;
    for (int t = tid; t < 4096; t += 256)
        q[t] = tile[t & 63][t >> 6];
}

// final: out = relu(bn(conv_out) + x_in)
__global__ void __launch_bounds__(256) final_k(const float* __restrict__ x_in,
                                               float* __restrict__ out) {
    int idx = blockIdx.x * 256 + threadIdx.x;
    int o = idx >> 15, m = idx & (NT - 1);
    int b = m >> 12, hw = m & 4095;
    float v = g_y2[idx] * g_sb[1376 + o] + g_sb[1376 + 256 + o];
    int oidx = (b * 256 + o) * 4096 + hw;
    v += x_in[oidx];
    out[oidx] = fmaxf(v, 0.f);
}

// ---------------------------------------------------------------------------
extern "C" void kernel_launch(void* const* d_in, const int* in_sizes, int n_in,
                              void* d_out, int out_size) {
    (void)in_sizes; (void)n_in; (void)out_size;
    const float* x_in   = (const float*)d_in[0];
    const float* w_in   = (const float*)d_in[1];
    const float* g_in   = (const float*)d_in[2];
    const float* b_in   = (const float*)d_in[3];
    const float* w_out  = (const float*)d_in[4];
    const float* g_out  = (const float*)d_in[5];
    const float* b_out  = (const float*)d_in[6];
    const float* wqkv_h = (const float*)d_in[7];
    const float* rel_h  = (const float*)d_in[8];
    const float* ga_h   = (const float*)d_in[9];
    const float* ba_h   = (const float*)d_in[10];
    const float* go_h   = (const float*)d_in[11];
    const float* bo_h   = (const float*)d_in[12];
    const float* wqkv_w = (const float*)d_in[13];
    const float* rel_w  = (const float*)d_in[14];
    const float* ga_w   = (const float*)d_in[15];
    const float* ba_w   = (const float*)d_in[16];
    const float* go_w   = (const float*)d_in[17];
    const float* bo_w   = (const float*)d_in[18];

    zero_stats<<<8, 256>>>();                                   // 0
    prep_S<<<23, 256>>>(rel_h, 0);                              // 1
    prep_S<<<23, 256>>>(rel_w, 1);                              // 2

    // conv-in (+stats) -> y1                                   // 3 (profiled)
    gemm_k<0><<<dim3(256, 1), 256>>>(w_in, x_in, 256);
    make_scale<<<2, 64>>>(0, g_in, b_in, 0, 128, 1.f / 32768.f);

    // --- axial attention along H ---
    gemm_k<1><<<dim3(256, 2), 256>>>(wqkv_h, nullptr, 128);
    att_stats<<<512, 256>>>(256, 0);
    make_scale<<<1, 64>>>(256, ga_h, ba_h, 256, 24, 1.f / 2097152.f);
    att_pass2<<<dim3(512, 8), 256>>>(rel_h, 256, 304);
    make_scale<<<4, 64>>>(304, go_h, bo_h, 304, 256, 1.f / 32768.f);
    combine1<<<dim3(128, 8), 256>>>();

    // --- axial attention along W ---
    gemm_k<2><<<dim3(256, 2), 256>>>(wqkv_w, nullptr, 128);
    att_stats<<<512, 256>>>(816, 1);
    make_scale<<<1, 64>>>(816, ga_w, ba_w, 816, 24, 1.f / 2097152.f);
    att_pass2<<<dim3(512, 8), 256>>>(rel_w, 816, 864);
    make_scale<<<4, 64>>>(864, go_w, bo_w, 864, 256, 1.f / 32768.f);

    // conv-out (fused combine2 at load, +stats) -> y2
    gemm_k<3><<<dim3(256, 2), 256>>>(w_out, nullptr, 128);
    make_scale<<<4, 64>>>(1376, g_out, b_out, 1376, 256, 1.f / 32768.f);

    final_k<<<32768, 256>>>(x_in, (float*)d_out);
}

// round 7
// speedup vs baseline: 1.1130x; 1.1130x over previous
#include <cuda_runtime.h>
#include <cstdint>

// ---------------------------------------------------------------------------
// Problem constants
//   B=8, C_IN=256, DIM=64, HEADS=8, D_IN=128, DKQ=8, DV=16, QKV=32
//   N = B*DIM*DIM = 32768 "pixels"; sequences: 512 of length 64
// ---------------------------------------------------------------------------
#define NT 32768
#define EPSV 1e-5f

__device__ float  g_y1[128 * NT];      // conv-in raw output, layout [c][b][w][h]
__device__ float  g_qkv[256 * NT];     // qkv, layout [o][bw][pos]
__device__ float  g_outatt[256 * NT];  // attention out (sve ch 0..127, sv 128..255)
__device__ float  g_x3[128 * NT];      // att1 combined (input to qkv2 GEMM)
__device__ float  g_y2[256 * NT];      // conv-out raw output [o][n1]
// stats offsets: convin @0(256) att1 @256(48) out1 @304(512) att2 @816(48)
//                out2 @864(512) convout @1376(512)
__device__ double g_st[1888];
__device__ float  g_sb[1888];

// Precomputed rel-embedding tables, double-buffered per direction
__device__ float g_Tq[2][8 * 64], g_Tk[2][8 * 64];
__device__ float g_Sq[2][36 * 64], g_Sk[2][36 * 64];

__device__ const int c_pi[36] = {0,0,0,0,0,0,0,0, 1,1,1,1,1,1,1, 2,2,2,2,2,2,
                                 3,3,3,3,3, 4,4,4,4, 5,5,5, 6,6, 7};
__device__ const int c_pj[36] = {0,1,2,3,4,5,6,7, 1,2,3,4,5,6,7, 2,3,4,5,6,7,
                                 3,4,5,6,7, 4,5,6,7, 5,6,7, 6,7, 7};

__global__ void zero_stats() {
    int i = blockIdx.x * 256 + threadIdx.x;
    if (i < 1888) g_st[i] = 0.0;
}

__global__ void make_scale(int stoff, const float* __restrict__ gamma,
                           const float* __restrict__ beta, int sboff, int C, float invN) {
    int t = blockIdx.x * 64 + threadIdx.x;
    if (t >= C) return;
    double mean = g_st[stoff + t] * (double)invN;
    double var  = g_st[stoff + C + t] * (double)invN - mean * mean;
    float s = gamma[t] * rsqrtf((float)var + EPSV);
    g_sb[sboff + t]     = s;
    g_sb[sboff + C + t] = beta[t] - (float)mean * s;
}

// ---------------------------------------------------------------------------
// 3xTF32 helpers
// ---------------------------------------------------------------------------
__device__ __forceinline__ void split_tf32(float x, float& hi, float& lo) {
    uint32_t h;
    asm("cvt.rna.tf32.f32 %0, %1;" : "=r"(h) : "f"(x));
    float hf = __uint_as_float(h);
    uint32_t l;
    asm("cvt.rna.tf32.f32 %0, %1;" : "=r"(l) : "f"(x - hf));
    hi = hf;
    lo = __uint_as_float(l);
}

#define MMA_TF32(c, a0, a1, a2, a3, b0, b1)                                    \
    asm volatile(                                                              \
        "mma.sync.aligned.m16n8k8.row.col.f32.tf32.tf32.f32 "                  \
        "{%0,%1,%2,%3}, {%4,%5,%6,%7}, {%8,%9}, {%0,%1,%2,%3};"                \
        : "+f"(c[0]), "+f"(c[1]), "+f"(c[2]), "+f"(c[3])                       \
        : "r"(a0), "r"(a1), "r"(a2), "r"(a3), "r"(b0), "r"(b1))

// ---------------------------------------------------------------------------
// GEMM via 3xTF32 mma.sync, fragment-major smem, conflict-free staging.
//   A frag (16m x 8k): word = frag*128 + ((m&7)*4+(k&3))*4 + rg -> LDS.128
//   B frag (8k x 8n):  word = frag*66  + lane*2 + rg            -> LDS.64
// MODE 0 conv-in (gather x_in, scatter to y1 + stats), 1 qkv (BN+relu at
// load), 2 qkv plain (reads x3), 3 conv-out (fused combine2 at load, +stats)
// Block tile 128x128, k-chunk 16; 8 warps, warp tile 64(m) x 32(n); 2 CTA/SM.
// ---------------------------------------------------------------------------
template <int MODE>
__device__ __forceinline__ float4 gemm_loadB(const float* __restrict__ Bext,
                                             int n0, int k, int nn) {
    if (MODE == 0) {
        return *(const float4*)&Bext[(n0 >> 12) * 1048576 + k * 4096 + (n0 & 4095) + nn];
    } else if (MODE == 3) {
        float4 a = *(const float4*)&g_outatt[k * NT + n0 + nn];
        float4 b = *(const float4*)&g_outatt[(128 + k) * NT + n0 + nn];
        float sA = g_sb[864 + k],       bA = g_sb[864 + 256 + k];
        float sB = g_sb[864 + 128 + k], bB = g_sb[864 + 256 + 128 + k];
        float4 v;
        v.x = fmaxf(a.x * sA + bA + b.x * sB + bB, 0.f);
        v.y = fmaxf(a.y * sA + bA + b.y * sB + bB, 0.f);
        v.z = fmaxf(a.z * sA + bA + b.z * sB + bB, 0.f);
        v.w = fmaxf(a.w * sA + bA + b.w * sB + bB, 0.f);
        return v;
    } else {
        const float* Bp = (MODE == 1) ? g_y1 : g_x3;
        float4 v = *(const float4*)&Bp[k * NT + n0 + nn];
        if (MODE == 1) {
            float s = g_sb[k], bi = g_sb[128 + k];
            v.x = fmaxf(fmaf(v.x, s, bi), 0.f);
            v.y = fmaxf(fmaf(v.y, s, bi), 0.f);
            v.z = fmaxf(fmaf(v.z, s, bi), 0.f);
            v.w = fmaxf(fmaf(v.w, s, bi), 0.f);
        }
        return v;
    }
}

template <int MODE>
__global__ void __launch_bounds__(256, 2) gemm_k(const float* __restrict__ A,
                                                 const float* __restrict__ Bext, int K) {
    __shared__ float Ash[2048], Asl[2048];     // 16 frags * 128
    __shared__ float Bsh[2112], Bsl[2112];     // 32 frags * 66
    __shared__ float ssum[128], ssq[128];
    const int n0 = blockIdx.x * 128;
    const int m0 = blockIdx.y * 128;
    const int tid = threadIdx.x;
    const int warp = tid >> 5, lane = tid & 31;
    const int lq = lane & 3, lr = lane >> 2;
    const int mb = (warp & 1) * 64;
    const int nb = (warp >> 1) * 32;

    float* Cp = (MODE == 0) ? g_y1 : ((MODE == 3) ? g_y2 : g_qkv);

    // A staging mapping: bank bits {k0,k1,k2,m0,m3} all vary within a warp
    const int kb  = lane & 7;           // k bits 0..2
    const int m0b = (lane >> 3) & 1;    // m bit 0
    const int m3b = (lane >> 4) & 1;    // m bit 3
    const int mwb = m0b + m3b * 8 + warp * 16;
    // B staging coordinates
    const int bkr0 = tid >> 5, bn4 = (tid & 31) * 4;

    float acc[4][4][4];
#pragma unroll
    for (int mt = 0; mt < 4; mt++)
#pragma unroll
        for (int nt = 0; nt < 4; nt++)
#pragma unroll
            for (int c = 0; c < 4; c++) acc[mt][nt][c] = 0.f;

    const int nchunk = K >> 4;
    for (int c0 = 0; c0 < nchunk; c0++) {
        const int k0 = c0 * 16;
        // ---- stage A (conflict-free scalar stores) ----
#pragma unroll
        for (int it = 0; it < 8; it++) {
            int k = kb + (it & 1) * 8;
            int m = mwb + ((it >> 1) & 3) * 2;
            float v = A[(m0 + m) * K + k0 + k];
            int frag = (k >> 3) * 8 + (m >> 4);
            int rg = ((k >> 2) & 1) * 2 + ((m >> 3) & 1);
            int word = frag * 128 + ((m & 7) * 4 + (k & 3)) * 4 + rg;
            float h, l;
            split_tf32(v, h, l);
            Ash[word] = h;
            Asl[word] = l;
        }
        // ---- stage B ----
#pragma unroll
        for (int r = 0; r < 2; r++) {
            int kr = bkr0 + r * 8;
            float4 v = gemm_loadB<MODE>(Bext, n0, k0 + kr, bn4);
            int fl = ((kr >> 3) & 1) * 16 + (bn4 >> 3);
            int rg = (kr >> 2) & 1;
            int base = fl * 66 + ((bn4 & 7) * 4 + (kr & 3)) * 2 + rg;
            float h, l;
            split_tf32(v.x, h, l); Bsh[base + 0]  = h; Bsl[base + 0]  = l;
            split_tf32(v.y, h, l); Bsh[base + 8]  = h; Bsl[base + 8]  = l;
            split_tf32(v.z, h, l); Bsh[base + 16] = h; Bsl[base + 16] = l;
            split_tf32(v.w, h, l); Bsh[base + 24] = h; Bsl[base + 24] = l;
        }
        __syncthreads();

        // ---- compute ----
#pragma unroll
        for (int ks = 0; ks < 2; ks++) {
            float2 bhv[4], blv[4];
#pragma unroll
            for (int nt = 0; nt < 4; nt++) {
                int ab = (ks * 16 + (nb >> 3) + nt) * 66 + lane * 2;
                bhv[nt] = *(const float2*)&Bsh[ab];
                blv[nt] = *(const float2*)&Bsl[ab];
            }
#pragma unroll
            for (int mt = 0; mt < 4; mt++) {
                int aa = (ks * 8 + (mb >> 4) + mt) * 128 + lane * 4;
                float4 ha = *(const float4*)&Ash[aa];
                float4 la = *(const float4*)&Asl[aa];
                uint32_t ah0 = __float_as_uint(ha.x), ah1 = __float_as_uint(ha.y);
                uint32_t ah2 = __float_as_uint(ha.z), ah3 = __float_as_uint(ha.w);
                uint32_t al0 = __float_as_uint(la.x), al1 = __float_as_uint(la.y);
                uint32_t al2 = __float_as_uint(la.z), al3 = __float_as_uint(la.w);
#pragma unroll
                for (int nt = 0; nt < 4; nt++) {
                    uint32_t bh0 = __float_as_uint(bhv[nt].x);
                    uint32_t bh1 = __float_as_uint(bhv[nt].y);
                    uint32_t bl0 = __float_as_uint(blv[nt].x);
                    uint32_t bl1 = __float_as_uint(blv[nt].y);
                    MMA_TF32(acc[mt][nt], ah0, ah1, ah2, ah3, bh0, bh1);
                    MMA_TF32(acc[mt][nt], al0, al1, al2, al3, bh0, bh1);
                    MMA_TF32(acc[mt][nt], ah0, ah1, ah2, ah3, bl0, bl1);
                }
            }
        }
        __syncthreads();
    }

    if (MODE == 0 || MODE == 3) {
        for (int t = tid; t < 128; t += 256) { ssum[t] = 0.f; ssq[t] = 0.f; }
        __syncthreads();
    }

    if (MODE == 0) {
        const int bb = n0 >> 12, hw0 = n0 & 4095;
#pragma unroll
        for (int mt = 0; mt < 4; mt++) {
#pragma unroll
            for (int half = 0; half < 2; half++) {
                int o = mb + mt * 16 + lr + half * 8;  // m0 == 0
                float rs = 0.f, rq = 0.f;
#pragma unroll
                for (int nt = 0; nt < 4; nt++) {
#pragma unroll
                    for (int cc = 0; cc < 2; cc++) {
                        int hw = hw0 + nb + nt * 8 + 2 * lq + cc;
                        float v = acc[mt][nt][half * 2 + cc];
                        Cp[o * NT + bb * 4096 + (hw & 63) * 64 + (hw >> 6)] = v;
                        rs += v; rq += v * v;
                    }
                }
                atomicAdd(&ssum[o], rs);
                atomicAdd(&ssq[o], rq);
            }
        }
    } else {
#pragma unroll
        for (int mt = 0; mt < 4; mt++) {
#pragma unroll
            for (int half = 0; half < 2; half++) {
                int o = m0 + mb + mt * 16 + lr + half * 8;
                float rs = 0.f, rq = 0.f;
#pragma unroll
                for (int nt = 0; nt < 4; nt++) {
                    float2 v2 = make_float2(acc[mt][nt][half * 2], acc[mt][nt][half * 2 + 1]);
                    *(float2*)&Cp[o * NT + n0 + nb + nt * 8 + 2 * lq] = v2;
                    if (MODE == 3) { rs += v2.x + v2.y; rq += v2.x * v2.x + v2.y * v2.y; }
                }
                if (MODE == 3) {
                    atomicAdd(&ssum[o - m0], rs);
                    atomicAdd(&ssq[o - m0], rq);
                }
            }
        }
    }

    if (MODE == 0 || MODE == 3) {
        __syncthreads();
        const int base = (MODE == 0) ? 0 : 1376;
        const int Csz  = (MODE == 0) ? 128 : 256;
        if (tid < 128) {
            atomicAdd(&g_st[base + m0 + tid], (double)ssum[tid]);
            atomicAdd(&g_st[base + Csz + m0 + tid], (double)ssq[tid]);
        }
    }
}

// ---------------------------------------------------------------------------
// prep_S: precompute sliding-window tables of the rel embedding (grid-stride).
// ---------------------------------------------------------------------------
__global__ void __launch_bounds__(256) prep_S(const float* __restrict__ rel, int dir) {
    __shared__ float r[16][127];
    for (int t = threadIdx.x; t < 16 * 127; t += 256) r[t / 127][t % 127] = rel[t];
    __syncthreads();
    const int g0 = blockIdx.x * 256 + threadIdx.x;
    const int gs = gridDim.x * 256;
    for (int t = g0; t < 1024; t += gs) {
        int which = t >> 9, i = (t >> 6) & 7, d = t & 63;
        const float* rr = r[which * 8 + i];
        float s = 0.f;
        for (int u = 0; u < 64; u++) s += rr[d + u];
        (which ? g_Tk[dir] : g_Tq[dir])[i * 64 + d] = s;
    }
    for (int t = g0; t < 4608; t += gs) {
        int which = t / 2304, rem = t % 2304, p = rem >> 6, d = rem & 63;
        const float* a = r[which * 8 + c_pi[p]];
        const float* b = r[which * 8 + c_pj[p]];
        float s = 0.f;
        for (int u = 0; u < 64; u++) s = fmaf(a[d + u], b[d + u], s);
        (which ? g_Sk[dir] : g_Sq[dir])[p * 64 + d] = s;
    }
}

// ---------------------------------------------------------------------------
// att_stats: BN statistics of qr/kr/dots without materializing logits.
// ---------------------------------------------------------------------------
__global__ void __launch_bounds__(256) att_stats(int stoff, int dir) {
    const int bw = blockIdx.x, tid = threadIdx.x;
    __shared__ float qT[8][512];   // [h][d*8 + i]
    __shared__ float kT[8][512];
    __shared__ float rsq[8][8], rsk[8][8], tqs[8][8], tks[8][8];

    for (int t = tid; t < 8192; t += 256) {
        int which = t >> 12, o = (t >> 6) & 63, d = t & 63;
        float v = g_qkv[(which * 64 + o) * NT + bw * 64 + d];
        int h = o & 7, i = o >> 3;
        if (which == 0) qT[h][d * 8 + i] = v; else kT[h][d * 8 + i] = v;
    }
    __syncthreads();

    const int h = tid >> 5, lane = tid & 31;
    const float* Tq = g_Tq[dir];
    const float* Tk = g_Tk[dir];
    const float* Sq = g_Sq[dir];
    const float* Sk = g_Sk[dir];
    if (lane < 8) {
        float s = 0.f;
        for (int d = 0; d < 64; d++) s += qT[h][d * 8 + lane];
        rsq[h][lane] = s;
    } else if (lane < 16) {
        int i = lane - 8; float s = 0.f;
        for (int d = 0; d < 64; d++) s += kT[h][d * 8 + i];
        rsk[h][i] = s;
    } else if (lane < 24) {
        int i = lane - 16; float s = 0.f;
        for (int d = 0; d < 64; d++) s = fmaf(qT[h][d * 8 + i], __ldg(&Tq[i * 64 + d]), s);
        tqs[h][i] = s;
    } else {
        int i = lane - 24; float s = 0.f;
        for (int d = 0; d < 64; d++) s = fmaf(kT[h][d * 8 + i], __ldg(&Tk[i * 64 + d]), s);
        tks[h][i] = s;
    }

    float dsq = 0.f, wq = 0.f, wk = 0.f;
    for (int p = lane; p < 36; p += 32) {
        int i = c_pi[p], i2 = c_pj[p];
        float m = (i == i2) ? 1.f : 2.f;
        float gq = 0.f, wqp = 0.f, gk = 0.f, wkp = 0.f;
        for (int d = 0; d < 64; d++) {
            float pq = qT[h][d * 8 + i] * qT[h][d * 8 + i2];
            gq += pq; wqp = fmaf(pq, __ldg(&Sq[p * 64 + d]), wqp);
            float pk = kT[h][d * 8 + i] * kT[h][d * 8 + i2];
            gk += pk; wkp = fmaf(pk, __ldg(&Sk[p * 64 + d]), wkp);
        }
        dsq = fmaf(m * gq, gk, dsq); wq = fmaf(m, wqp, wq); wk = fmaf(m, wkp, wk);
    }
#pragma unroll
    for (int off = 16; off; off >>= 1) {
        dsq += __shfl_xor_sync(~0u, dsq, off);
        wq  += __shfl_xor_sync(~0u, wq,  off);
        wk  += __shfl_xor_sync(~0u, wk,  off);
    }
    __syncwarp();
    if (lane == 0) {
        float ds = 0.f, qs = 0.f, ks = 0.f;
#pragma unroll
        for (int i = 0; i < 8; i++) {
            ds = fmaf(rsq[h][i], rsk[h][i], ds);
            qs += tqs[h][i]; ks += tks[h][i];
        }
        atomicAdd(&g_st[stoff + h * 3 + 0], (double)qs);
        atomicAdd(&g_st[stoff + h * 3 + 1], (double)ks);
        atomicAdd(&g_st[stoff + h * 3 + 2], (double)ds);
        atomicAdd(&g_st[stoff + 24 + h * 3 + 0], (double)wq);
        atomicAdd(&g_st[stoff + 24 + h * 3 + 1], (double)wk);
        atomicAdd(&g_st[stoff + 24 + h * 3 + 2], (double)dsq);
    }
}

// ---------------------------------------------------------------------------
// att_pass2: logits (BN applied) -> softmax -> sv & sve.  Conflict-free:
// Phase A: warp = 8 d-rows, lane = j (stride-1 rel reads, broadcast q/k).
// Phase B: warp = 2 i-channels, lane = d (stride-1 rel, pitch-65 sat).
// ---------------------------------------------------------------------------
__global__ void __launch_bounds__(256) att_pass2(const float* __restrict__ rel,
                                                 int sba, int sto) {
    const int bw = blockIdx.x, h = blockIdx.y, tid = threadIdx.x;
    const int warp = tid >> 5, lane = tid & 31;
    __shared__ float sq[8][65], sk[8][65], svv[16][65];
    __shared__ float srel[32][129];
    __shared__ float sat[64][65];

#pragma unroll
    for (int r = 0; r < 8; r++) {
        int t = tid + r * 256;
        int o = t >> 6, d = t & 63;
        float v = g_qkv[(o * 8 + h) * NT + bw * 64 + d];
        if (o < 8) sq[o][d] = v;
        else if (o < 16) sk[o - 8][d] = v;
        else svv[o - 16][d] = v;
    }
    for (int t = tid; t < 32 * 127; t += 256) srel[t / 127][t % 127] = rel[t];
    const float s0 = g_sb[sba + h * 3], s1v = g_sb[sba + h * 3 + 1], s2v = g_sb[sba + h * 3 + 2];
    const float bsum = g_sb[sba + 24 + h * 3] + g_sb[sba + 24 + h * 3 + 1]
                     + g_sb[sba + 24 + h * 3 + 2];
    __syncthreads();

    {   // ---- Phase A: logits + softmax.  j0 = lane, j1 = lane + 32. ----
        float kk0[8], kk1[8];
#pragma unroll
        for (int i = 0; i < 8; i++) {
            kk0[i] = sk[i][lane];
            kk1[i] = sk[i][lane + 32];
        }
        const int dbase = warp * 8;
#pragma unroll
        for (int r = 0; r < 8; r++) {
            const int d = dbase + r;
            const int m0 = d - lane + 63;   // in [32,126]; m0-32 in [0,94]
            float qr0 = 0, kr0 = 0, dt0 = 0, qr1 = 0, kr1 = 0, dt1 = 0;
#pragma unroll
            for (int i = 0; i < 8; i++) {
                float qi  = sq[i][d];       // broadcast
                float kdi = sk[i][d];       // broadcast
                float rq0 = srel[i][m0],     rq1 = srel[i][m0 - 32];
                float rk0 = srel[8 + i][m0], rk1 = srel[8 + i][m0 - 32];
                qr0 = fmaf(qi, rq0, qr0);   qr1 = fmaf(qi, rq1, qr1);
                kr0 = fmaf(kdi, rk0, kr0);  kr1 = fmaf(kdi, rk1, kr1);
                dt0 = fmaf(qi, kk0[i], dt0); dt1 = fmaf(qi, kk1[i], dt1);
            }
            float l0 = qr0 * s0 + kr0 * s1v + dt0 * s2v + bsum;
            float l1 = qr1 * s0 + kr1 * s1v + dt1 * s2v + bsum;
            float mx = fmaxf(l0, l1);
#pragma unroll
            for (int off = 16; off; off >>= 1)
                mx = fmaxf(mx, __shfl_xor_sync(~0u, mx, off));
            float e0 = __expf(l0 - mx), e1 = __expf(l1 - mx);
            float se = e0 + e1;
#pragma unroll
            for (int off = 16; off; off >>= 1)
                se += __shfl_xor_sync(~0u, se, off);
            float inv = 1.f / se;
            sat[d][lane]      = e0 * inv;
            sat[d][lane + 32] = e1 * inv;
        }
    }
    __syncthreads();

    {   // ---- Phase B: sv & sve.  i0 = 2*warp, i1 = i0+1; da = lane, db = lane+32.
        const int i0 = warp * 2, i1 = i0 + 1;
        const int da = lane, db = lane + 32;
        float av0a = 0, av0b = 0, av1a = 0, av1b = 0;
        float ae0a = 0, ae0b = 0, ae1a = 0, ae1b = 0;
        const float* r0 = &srel[16 + i0][0];
        const float* r1 = &srel[16 + i1][0];
#pragma unroll 4
        for (int j = 0; j < 64; j++) {
            float Aa = sat[da][j];          // stride 65 across lanes: cf
            float Ab = sat[db][j];
            float v0 = svv[i0][j], v1 = svv[i1][j];   // broadcast
            float r0a = r0[da - j + 63], r0b = r0[db - j + 63];
            float r1a = r1[da - j + 63], r1b = r1[db - j + 63];
            av0a = fmaf(Aa, v0, av0a);  av0b = fmaf(Ab, v0, av0b);
            av1a = fmaf(Aa, v1, av1a);  av1b = fmaf(Ab, v1, av1b);
            ae0a = fmaf(Aa, r0a, ae0a); ae0b = fmaf(Ab, r0b, ae0b);
            ae1a = fmaf(Aa, r1a, ae1a); ae1b = fmaf(Ab, r1b, ae1b);
        }
        const int ch0 = h * 16 + i0, ch1 = h * 16 + i1;
        g_outatt[ch0 * NT + bw * 64 + da] = ae0a;
        g_outatt[ch0 * NT + bw * 64 + db] = ae0b;
        g_outatt[ch1 * NT + bw * 64 + da] = ae1a;
        g_outatt[ch1 * NT + bw * 64 + db] = ae1b;
        g_outatt[(128 + ch0) * NT + bw * 64 + da] = av0a;
        g_outatt[(128 + ch0) * NT + bw * 64 + db] = av0b;
        g_outatt[(128 + ch1) * NT + bw * 64 + da] = av1a;
        g_outatt[(128 + ch1) * NT + bw * 64 + db] = av1b;

        float se0 = ae0a + ae0b, qe0 = ae0a * ae0a + ae0b * ae0b;
        float se1 = ae1a + ae1b, qe1 = ae1a * ae1a + ae1b * ae1b;
        float sv0 = av0a + av0b, qv0 = av0a * av0a + av0b * av0b;
        float sv1 = av1a + av1b, qv1 = av1a * av1a + av1b * av1b;
#pragma unroll
        for (int off = 16; off; off >>= 1) {
            se0 += __shfl_xor_sync(~0u, se0, off); qe0 += __shfl_xor_sync(~0u, qe0, off);
            se1 += __shfl_xor_sync(~0u, se1, off); qe1 += __shfl_xor_sync(~0u, qe1, off);
            sv0 += __shfl_xor_sync(~0u, sv0, off); qv0 += __shfl_xor_sync(~0u, qv0, off);
            sv1 += __shfl_xor_sync(~0u, sv1, off); qv1 += __shfl_xor_sync(~0u, qv1, off);
        }
        if (lane == 0) {
            atomicAdd(&g_st[sto + ch0], (double)se0);
            atomicAdd(&g_st[sto + ch1], (double)se1);
            atomicAdd(&g_st[sto + 256 + ch0], (double)qe0);
            atomicAdd(&g_st[sto + 256 + ch1], (double)qe1);
            atomicAdd(&g_st[sto + 128 + ch0], (double)sv0);
            atomicAdd(&g_st[sto + 128 + ch1], (double)sv1);
            atomicAdd(&g_st[sto + 256 + 128 + ch0], (double)qv0);
            atomicAdd(&g_st[sto + 256 + 128 + ch1], (double)qv1);
        }
    }
}

// combine att1: x3[c][b][h][w] = bn(sve) + bn(sv), with h<->w transpose
__global__ void __launch_bounds__(256) combine1() {
    const int c = blockIdx.x, b = blockIdx.y, tid = threadIdx.x;
    __shared__ float tile[64][65];
    const float sA = g_sb[304 + c],        bA = g_sb[304 + 256 + c];
    const float sB = g_sb[304 + c + 128],  bB = g_sb[304 + 256 + c + 128];
    const float* pA = g_outatt + c * NT + b * 4096;
    const float* pB = g_outatt + (c + 128) * NT + b * 4096;
    for (int t = tid; t < 4096; t += 256)
        tile[t >> 6][t & 63] = pA[t] * sA + bA + pB[t] * sB + bB;
    __syncthreads();
    float* q = g_x3 + c * NT + b * 4096;
    for (int t = tid; t < 4096; t += 256)
        q[t] = tile[t & 63][t >> 6];
}

// final: out = relu(bn(conv_out) + x_in)
__global__ void __launch_bounds__(256) final_k(const float* __restrict__ x_in,
                                               float* __restrict__ out) {
    int idx = blockIdx.x * 256 + threadIdx.x;
    int o = idx >> 15, m = idx & (NT - 1);
    int b = m >> 12, hw = m & 4095;
    float v = g_y2[idx] * g_sb[1376 + o] + g_sb[1376 + 256 + o];
    int oidx = (b * 256 + o) * 4096 + hw;
    v += x_in[oidx];
    out[oidx] = fmaxf(v, 0.f);
}

// ---------------------------------------------------------------------------
extern "C" void kernel_launch(void* const* d_in, const int* in_sizes, int n_in,
                              void* d_out, int out_size) {
    (void)in_sizes; (void)n_in; (void)out_size;
    const float* x_in   = (const float*)d_in[0];
    const float* w_in   = (const float*)d_in[1];
    const float* g_in   = (const float*)d_in[2];
    const float* b_in   = (const float*)d_in[3];
    const float* w_out  = (const float*)d_in[4];
    const float* g_out  = (const float*)d_in[5];
    const float* b_out  = (const float*)d_in[6];
    const float* wqkv_h = (const float*)d_in[7];
    const float* rel_h  = (const float*)d_in[8];
    const float* ga_h   = (const float*)d_in[9];
    const float* ba_h   = (const float*)d_in[10];
    const float* go_h   = (const float*)d_in[11];
    const float* bo_h   = (const float*)d_in[12];
    const float* wqkv_w = (const float*)d_in[13];
    const float* rel_w  = (const float*)d_in[14];
    const float* ga_w   = (const float*)d_in[15];
    const float* ba_w   = (const float*)d_in[16];
    const float* go_w   = (const float*)d_in[17];
    const float* bo_w   = (const float*)d_in[18];

    zero_stats<<<8, 256>>>();                                   // 0
    prep_S<<<23, 256>>>(rel_h, 0);                              // 1
    prep_S<<<23, 256>>>(rel_w, 1);                              // 2

    // conv-in (+stats) -> y1                                   // 3 (profiled)
    gemm_k<0><<<dim3(256, 1), 256>>>(w_in, x_in, 256);
    make_scale<<<2, 64>>>(0, g_in, b_in, 0, 128, 1.f / 32768.f);

    // --- axial attention along H ---
    gemm_k<1><<<dim3(256, 2), 256>>>(wqkv_h, nullptr, 128);
    att_stats<<<512, 256>>>(256, 0);
    make_scale<<<1, 64>>>(256, ga_h, ba_h, 256, 24, 1.f / 2097152.f);
    att_pass2<<<dim3(512, 8), 256>>>(rel_h, 256, 304);
    make_scale<<<4, 64>>>(304, go_h, bo_h, 304, 256, 1.f / 32768.f);
    combine1<<<dim3(128, 8), 256>>>();

    // --- axial attention along W ---
    gemm_k<2><<<dim3(256, 2), 256>>>(wqkv_w, nullptr, 128);
    att_stats<<<512, 256>>>(816, 1);
    make_scale<<<1, 64>>>(816, ga_w, ba_w, 816, 24, 1.f / 2097152.f);
    att_pass2<<<dim3(512, 8), 256>>>(rel_w, 816, 864);
    make_scale<<<4, 64>>>(864, go_w, bo_w, 864, 256, 1.f / 32768.f);

    // conv-out (fused combine2 at load, +stats) -> y2
    gemm_k<3><<<dim3(256, 2), 256>>>(w_out, nullptr, 128);
    make_scale<<<4, 64>>>(1376, g_out, b_out, 1376, 256, 1.f / 32768.f);

    final_k<<<32768, 256>>>(x_in, (float*)d_out);
}